// round 7
// baseline (speedup 1.0000x reference)
#include <cuda_runtime.h>
#include <cstddef>

// ---------------------------------------------------------------------------
// Problem constants
// ---------------------------------------------------------------------------
#define HW    16384            // 128*128
#define NCHW  4194304          // 4*64*16384
#define WSZ   102400           // 64*25*64 (per-layer weight count)

typedef unsigned long long u64;

// ---------------------------------------------------------------------------
// Scratch: __device__ globals (module-load allocation; no cudaMalloc)
// ---------------------------------------------------------------------------
__device__ float g_A[NCHW];                 // ping
__device__ float g_B[NCHW];                 // pong
__device__ float g_T[3ull * NCHW];          // t0..t2 (t3 never read)
__device__ u64   g_wfd[3 * WSZ];            // fwd weights, lane-duplicated f32x2: [l][ci][uv][co]
__device__ u64   g_wbd[3 * WSZ];            // bwd weights (transposed+flipped), dup'd
__device__ u64   g_w0d[25 * 64];            // conv0 weights dup'd: [uv][co]
__device__ float g_w0b[64 * 25];            // final convT weights [a][ky][kx] (flipped)
__device__ float g_actp[4 * 64 * 80];       // padded act tables: [l][c][80], data at +8

// ---------------------------------------------------------------------------
// Packed f32x2 helpers (sm_100a)
// ---------------------------------------------------------------------------
__device__ __forceinline__ u64 pk2(float lo, float hi) {
    u64 r;
    asm("mov.b64 %0, {%1, %2};" : "=l"(r) : "f"(lo), "f"(hi));
    return r;
}
__device__ __forceinline__ void fma2(u64& d, u64 a, u64 b) {
    asm("fma.rn.f32x2 %0, %1, %2, %0;" : "+l"(d) : "l"(a), "l"(b));
}
__device__ __forceinline__ float2 upk(u64 v) {
    float2 r;
    asm("mov.b64 {%0, %1}, %2;" : "=f"(r.x), "=f"(r.y) : "l"(v));
    return r;
}

// ---------------------------------------------------------------------------
// RBF mixture activation, windowed (|k|<=6) stable recurrence.
//   f(v) = sum_p w[p] exp(-(v-mu_p)^2/200),  mu_p = -310 + 10 p
//   exp(-(d0-10k)^2/200) = E0 * a^k * e^{-k^2/2},  E0=e^{-d0^2/200}, a=e^{d0/10}
// wrow points at p=0 of a zero-padded row (8 left / 9 right) -> branch free.
// ---------------------------------------------------------------------------
__device__ __forceinline__ float act_fwd(float v, const float* __restrict__ wrow) {
    float pf = rintf((v + 310.f) * 0.1f);
    pf = fminf(fmaxf(pf, 0.f), 62.f);
    float d0 = v + 310.f - 10.f * pf;
    d0 = fminf(fmaxf(d0, -55.f), 55.f);
    float a  = __expf(0.1f * d0);
    float ai = __expf(-0.1f * d0);
    float E0 = __expf(-0.005f * d0 * d0);
    const float* w = wrow + (int)pf;
    const float CK[7] = {0.f, 0.60653066f, 0.22313016f, 0.082084999f,
                         0.030197383f, 0.011108997f, 0.0040867714f};
    float s = w[0];
    float up = 1.f, un = 1.f;
#pragma unroll
    for (int k = 1; k <= 6; k++) {
        up *= a  * CK[k];
        un *= ai * CK[k];
        s += w[k] * up + w[-k] * un;
    }
    return E0 * s;
}

// f'(v) = -(1/100) * E0 * (d0*s - 10*s1),  s1 = sum_k k w_k u_k
__device__ __forceinline__ float act_grad(float v, const float* __restrict__ wrow) {
    float pf = rintf((v + 310.f) * 0.1f);
    pf = fminf(fmaxf(pf, 0.f), 62.f);
    float d0 = v + 310.f - 10.f * pf;
    d0 = fminf(fmaxf(d0, -55.f), 55.f);
    float a  = __expf(0.1f * d0);
    float ai = __expf(-0.1f * d0);
    float E0 = __expf(-0.005f * d0 * d0);
    const float* w = wrow + (int)pf;
    const float CK[7] = {0.f, 0.60653066f, 0.22313016f, 0.082084999f,
                         0.030197383f, 0.011108997f, 0.0040867714f};
    float s = w[0], s1 = 0.f;
    float up = 1.f, un = 1.f;
#pragma unroll
    for (int k = 1; k <= 6; k++) {
        up *= a  * CK[k];
        un *= ai * CK[k];
        float tp = w[k]  * up;
        float tm = w[-k] * un;
        s  += tp + tm;
        s1 += (float)k * (tp - tm);
    }
    return -0.01f * E0 * (d0 * s - 10.f * s1);
}

// ---------------------------------------------------------------------------
// Weight / table prep (duplicate each weight into both f32x2 lanes)
// ---------------------------------------------------------------------------
__device__ __forceinline__ u64 dupf(float v) {
    u64 u = (u64)__float_as_uint(v);
    return u | (u << 32);
}

__global__ void prep_kernel(const float* __restrict__ f0,
                            const float* __restrict__ fr,
                            const float* __restrict__ actw) {
    int idx = blockIdx.x * 256 + threadIdx.x;
    if (idx < 3 * WSZ) {
        int co = idx & 63;
        int r  = idx >> 6;
        int kx = r % 5; r /= 5;
        int ky = r % 5; r /= 5;
        int ci = r & 63;
        int l  = r >> 6;
        // fwd: wfd[l][ci][ky][kx][co] = fr[l][co][ci][ky][kx]
        g_wfd[idx] = dupf(fr[(((l * 64 + co) * 64 + ci) * 25) + ky * 5 + kx]);
        // bwd (conv_t as zero-padded corr): wbd[l][a][ky][kx][b] = fr[l][a][b][4-ky][4-kx]
        g_wbd[idx] = dupf(fr[(((l * 64 + ci) * 64 + co) * 25) + (4 - ky) * 5 + (4 - kx)]);
    }
    if (idx < 1600) {
        int co = idx & 63;
        int r  = idx >> 6;
        int kx = r % 5, ky = r / 5;
        g_w0d[idx] = dupf(f0[co * 25 + ky * 5 + kx]);     // [ky][kx][co]
        int a = idx / 25, q = idx % 25;
        int u = q / 5, v = q % 5;
        g_w0b[idx] = f0[a * 25 + (4 - u) * 5 + (4 - v)];  // [a][u][v], flipped
    }
    if (idx < 4 * 64 * 80) {
        int q  = (idx % 80) - 8;
        int lc = idx / 80;
        g_actp[idx] = (q >= 0 && q < 63) ? actw[lc * 63 + q] : 0.f;
    }
}

// ---------------------------------------------------------------------------
// Main conv kernel. Tile 32x8 px, 256 threads; thread = 8 px (4 row-pairs)
// x 8 co, accumulated as 32 packed f32x2 (fma.rn.f32x2 -> 2x fp32 rate).
// Weights: lane-duplicated [ci][uv][co] -> warp-uniform LDG.128 of packed ops.
// FWD: replication pad, +bias, store conv (tout if STORE_T) and act (out).
// BWD: zero pad, epilogue gate by act_grad(tg), store to out.
// ---------------------------------------------------------------------------
template <bool BWD, int NCI, bool STORE_T>
__global__ __launch_bounds__(256, 2)
void conv_kernel(const float* __restrict__ in, float inscale,
                 const u64* __restrict__ w,
                 const float* __restrict__ bias,
                 const float* __restrict__ actp,
                 const float* __restrict__ tg,
                 float* __restrict__ tout,
                 float* __restrict__ out) {
    __shared__ float s_act[64 * 80];
    __shared__ float s_in[12 * 36];
    const int tid = threadIdx.x;
    const int x   = tid & 31;
    const int wid = tid >> 5;                  // co octet
    const int n   = blockIdx.z;
    const int tx0 = blockIdx.x * 32, ty0 = blockIdx.y * 8;

    for (int i = tid; i < 64 * 80; i += 256) s_act[i] = actp[i];

    u64 acc[32];
#pragma unroll
    for (int i = 0; i < 32; i++) acc[i] = 0ull;

    for (int ci = 0; ci < NCI; ci++) {
        __syncthreads();                        // also covers s_act on first iter
        const float* ip = in + ((size_t)(n * NCI + ci)) * HW;
        for (int i = tid; i < 432; i += 256) {
            int py = i / 36, px = i - py * 36;
            int gy = ty0 + py - 2, gx = tx0 + px - 2;
            float v;
            if (BWD) {
                v = (gy >= 0 && gy < 128 && gx >= 0 && gx < 128) ? ip[gy * 128 + gx] : 0.f;
            } else {
                gy = min(max(gy, 0), 127);
                gx = min(max(gx, 0), 127);
                v = ip[gy * 128 + gx] * inscale;
            }
            s_in[i] = v;
        }
        __syncthreads();
        const u64* wp = w + ci * 1600 + wid * 8;
#pragma unroll
        for (int u = 0; u < 5; u++) {
#pragma unroll
            for (int v = 0; v < 5; v++) {
                const ulonglong2* wq = reinterpret_cast<const ulonglong2*>(wp + (u * 5 + v) * 64);
                ulonglong2 wA = __ldg(wq);
                ulonglong2 wB = __ldg(wq + 1);
                ulonglong2 wC = __ldg(wq + 2);
                ulonglong2 wD = __ldg(wq + 3);
                u64 ivp[4];
#pragma unroll
                for (int p = 0; p < 4; p++)
                    ivp[p] = pk2(s_in[(2 * p     + u) * 36 + x + v],
                                 s_in[(2 * p + 1 + u) * 36 + x + v]);
#pragma unroll
                for (int p = 0; p < 4; p++) {
                    fma2(acc[p * 8 + 0], ivp[p], wA.x);
                    fma2(acc[p * 8 + 1], ivp[p], wA.y);
                    fma2(acc[p * 8 + 2], ivp[p], wB.x);
                    fma2(acc[p * 8 + 3], ivp[p], wB.y);
                    fma2(acc[p * 8 + 4], ivp[p], wC.x);
                    fma2(acc[p * 8 + 5], ivp[p], wC.y);
                    fma2(acc[p * 8 + 6], ivp[p], wD.x);
                    fma2(acc[p * 8 + 7], ivp[p], wD.y);
                }
            }
        }
    }

    // Epilogue
#pragma unroll
    for (int c = 0; c < 8; c++) {
        const int co = wid * 8 + c;
        const float* wrow = &s_act[co * 80 + 8];
        const float b = BWD ? 0.f : bias[co];
        size_t base = ((size_t)(n * 64 + co)) * HW + (size_t)ty0 * 128 + tx0 + x;
#pragma unroll
        for (int p = 0; p < 4; p++) {
            float2 vv = upk(acc[p * 8 + c]);
            size_t i0 = base + (size_t)(2 * p) * 128;
            size_t i1 = i0 + 128;
            float v0 = vv.x + b;
            float v1 = vv.y + b;
            if (BWD) {
                out[i0] = v0 * act_grad(tg[i0], wrow);
                out[i1] = v1 * act_grad(tg[i1], wrow);
            } else {
                if (STORE_T) { tout[i0] = v0; tout[i1] = v1; }
                out[i0] = act_fwd(v0, wrow);
                out[i1] = act_fwd(v1, wrow);
            }
        }
    }
}

// ---------------------------------------------------------------------------
// Final: r = crop(conv_t(in, f0)) (64->1, zero pad), out = x - r/255 - e^lam*(x-y)
// ci chunked by 4.
// ---------------------------------------------------------------------------
__global__ __launch_bounds__(256)
void final_kernel(const float* __restrict__ in,
                  const float* __restrict__ xin,
                  const float* __restrict__ yin,
                  const float* __restrict__ lam,
                  float* __restrict__ out) {
    __shared__ float s_w[1600];
    __shared__ float s_in[4 * 432];
    const int tid = threadIdx.x;
    const int x   = tid & 31;
    const int yy  = tid >> 5;
    const int n   = blockIdx.z;
    const int tx0 = blockIdx.x * 32, ty0 = blockIdx.y * 8;

    for (int i = tid; i < 1600; i += 256) s_w[i] = g_w0b[i];

    float acc = 0.f;
    for (int c0 = 0; c0 < 64; c0 += 4) {
        __syncthreads();
        for (int i = tid; i < 4 * 432; i += 256) {
            int cc = i / 432, j = i - cc * 432;
            int py = j / 36, px = j - py * 36;
            int gy = ty0 + py - 2, gx = tx0 + px - 2;
            const float* ip = in + ((size_t)(n * 64 + c0 + cc)) * HW;
            s_in[i] = (gy >= 0 && gy < 128 && gx >= 0 && gx < 128) ? ip[gy * 128 + gx] : 0.f;
        }
        __syncthreads();
#pragma unroll
        for (int cc = 0; cc < 4; cc++) {
            const float* wp  = &s_w[(c0 + cc) * 25];
            const float* pin = s_in + cc * 432;
#pragma unroll
            for (int u = 0; u < 5; u++)
#pragma unroll
                for (int v = 0; v < 5; v++)
                    acc += pin[(yy + u) * 36 + x + v] * wp[u * 5 + v];
        }
    }
    size_t idx = (size_t)n * HW + (size_t)(ty0 + yy) * 128 + tx0 + x;
    float xv = xin[idx], yv = yin[idx];
    float el = __expf(lam[0]);
    out[idx] = xv - acc * (1.f / 255.f) - el * (xv - yv);
}

// ---------------------------------------------------------------------------
// Launch
// ---------------------------------------------------------------------------
extern "C" void kernel_launch(void* const* d_in, const int* in_sizes, int n_in,
                              void* d_out, int out_size) {
    const float *x = nullptr, *y = nullptr, *lam = nullptr, *f0 = nullptr,
                *fr = nullptr, *bias = nullptr, *actw = nullptr;
    for (int i = 0; i < n_in; i++) {
        const float* p = (const float*)d_in[i];
        switch (in_sizes[i]) {
            case 65536: if (!x) x = p; else y = p; break;   // x first, y second (metadata order)
            case 1:      lam  = p; break;
            case 1600:   f0   = p; break;
            case 307200: fr   = p; break;
            case 256:    bias = p; break;
            case 16128:  actw = p; break;
            default: break;
        }
    }

    void *pA, *pB, *pT, *pwf, *pwb, *pw0, *pact;
    cudaGetSymbolAddress(&pA, g_A);
    cudaGetSymbolAddress(&pB, g_B);
    cudaGetSymbolAddress(&pT, g_T);
    cudaGetSymbolAddress(&pwf, g_wfd);
    cudaGetSymbolAddress(&pwb, g_wbd);
    cudaGetSymbolAddress(&pw0, g_w0d);
    cudaGetSymbolAddress(&pact, g_actp);
    float* A   = (float*)pA;
    float* B   = (float*)pB;
    float* T   = (float*)pT;
    u64*   wf  = (u64*)pwf;
    u64*   wb  = (u64*)pwb;
    u64*   w0  = (u64*)pw0;
    float* act = (float*)pact;

    dim3 grid(4, 16, 4), blk(256);

    prep_kernel<<<1200, 256>>>(f0, fr, actw);

    // forward: conv0 (1->64, x255) then layers 1..3 (t3 never read -> no store)
    conv_kernel<false, 1,  true ><<<grid, blk>>>(x, 255.f, w0,           bias,       act,            nullptr,          T,                A);
    conv_kernel<false, 64, true ><<<grid, blk>>>(A, 1.f,   wf,           bias + 64,  act + 5120,     nullptr,          T + (size_t)NCHW, B);
    conv_kernel<false, 64, true ><<<grid, blk>>>(B, 1.f,   wf + WSZ,     bias + 128, act + 2 * 5120, nullptr,          T + 2ull * NCHW,  A);
    conv_kernel<false, 64, false><<<grid, blk>>>(A, 1.f,   wf + 2 * WSZ, bias + 192, act + 3 * 5120, nullptr,          nullptr,          B);

    // backward: convT(l) with act_grad(t_{l-1}) gate fused in epilogue
    conv_kernel<true, 64, false><<<grid, blk>>>(B, 1.f, wb + 2 * WSZ, nullptr, act + 2 * 5120, T + 2ull * NCHW,  nullptr, A);
    conv_kernel<true, 64, false><<<grid, blk>>>(A, 1.f, wb + WSZ,     nullptr, act + 5120,     T + (size_t)NCHW, nullptr, B);
    conv_kernel<true, 64, false><<<grid, blk>>>(B, 1.f, wb,           nullptr, act,            T,                nullptr, A);

    // final convT (64->1) + combine
    final_kernel<<<grid, blk>>>(A, x, y, lam, (float*)d_out);
}

// round 8
// speedup vs baseline: 1.0029x; 1.0029x over previous
#include <cuda_runtime.h>
#include <cstddef>

// ---------------------------------------------------------------------------
// Problem constants
// ---------------------------------------------------------------------------
#define HW    16384            // 128*128
#define NCHW  4194304          // 4*64*16384
#define WSZ   102400           // 64*25*64 (per-layer weight count)

typedef unsigned long long u64;

// ---------------------------------------------------------------------------
// Scratch: __device__ globals (module-load allocation; no cudaMalloc)
// ---------------------------------------------------------------------------
__device__ float g_A[NCHW];                 // ping
__device__ float g_B[NCHW];                 // pong
__device__ float g_T[3ull * NCHW];          // t0..t2 (t3 never read)
__device__ u64   g_wfd[3 * WSZ];            // fwd weights, lane-duplicated f32x2: [l][ci][uv][co]
__device__ u64   g_wbd[3 * WSZ];            // bwd weights (transposed+flipped), dup'd
__device__ u64   g_w0d[25 * 64];            // conv0 weights dup'd: [uv][co]
__device__ float g_w0b[64 * 25];            // final convT weights [a][ky][kx] (flipped)
__device__ float g_actp[4 * 64 * 80];       // padded act tables: [l][c][80], data at +8

// ---------------------------------------------------------------------------
// Packed f32x2 helpers (sm_100a)
// ---------------------------------------------------------------------------
__device__ __forceinline__ u64 pk2(float lo, float hi) {
    u64 r;
    asm("mov.b64 %0, {%1, %2};" : "=l"(r) : "f"(lo), "f"(hi));
    return r;
}
__device__ __forceinline__ void fma2(u64& d, u64 a, u64 b) {
    asm("fma.rn.f32x2 %0, %1, %2, %0;" : "+l"(d) : "l"(a), "l"(b));
}
__device__ __forceinline__ float2 upk(u64 v) {
    float2 r;
    asm("mov.b64 {%0, %1}, %2;" : "=f"(r.x), "=f"(r.y) : "l"(v));
    return r;
}

// ---------------------------------------------------------------------------
// RBF mixture activation, windowed (|k|<=6) stable recurrence.
//   f(v) = sum_p w[p] exp(-(v-mu_p)^2/200),  mu_p = -310 + 10 p
//   exp(-(d0-10k)^2/200) = E0 * a^k * e^{-k^2/2},  E0=e^{-d0^2/200}, a=e^{d0/10}
// wrow points at p=0 of a zero-padded row (8 left / 9 right) -> branch free.
// ---------------------------------------------------------------------------
__device__ __forceinline__ float act_fwd(float v, const float* __restrict__ wrow) {
    float pf = rintf((v + 310.f) * 0.1f);
    pf = fminf(fmaxf(pf, 0.f), 62.f);
    float d0 = v + 310.f - 10.f * pf;
    d0 = fminf(fmaxf(d0, -55.f), 55.f);
    float a  = __expf(0.1f * d0);
    float ai = __expf(-0.1f * d0);
    float E0 = __expf(-0.005f * d0 * d0);
    const float* w = wrow + (int)pf;
    const float CK[7] = {0.f, 0.60653066f, 0.22313016f, 0.082084999f,
                         0.030197383f, 0.011108997f, 0.0040867714f};
    float s = w[0];
    float up = 1.f, un = 1.f;
#pragma unroll
    for (int k = 1; k <= 6; k++) {
        up *= a  * CK[k];
        un *= ai * CK[k];
        s += w[k] * up + w[-k] * un;
    }
    return E0 * s;
}

// f'(v) = -(1/100) * E0 * (d0*s - 10*s1),  s1 = sum_k k w_k u_k
__device__ __forceinline__ float act_grad(float v, const float* __restrict__ wrow) {
    float pf = rintf((v + 310.f) * 0.1f);
    pf = fminf(fmaxf(pf, 0.f), 62.f);
    float d0 = v + 310.f - 10.f * pf;
    d0 = fminf(fmaxf(d0, -55.f), 55.f);
    float a  = __expf(0.1f * d0);
    float ai = __expf(-0.1f * d0);
    float E0 = __expf(-0.005f * d0 * d0);
    const float* w = wrow + (int)pf;
    const float CK[7] = {0.f, 0.60653066f, 0.22313016f, 0.082084999f,
                         0.030197383f, 0.011108997f, 0.0040867714f};
    float s = w[0], s1 = 0.f;
    float up = 1.f, un = 1.f;
#pragma unroll
    for (int k = 1; k <= 6; k++) {
        up *= a  * CK[k];
        un *= ai * CK[k];
        float tp = w[k]  * up;
        float tm = w[-k] * un;
        s  += tp + tm;
        s1 += (float)k * (tp - tm);
    }
    return -0.01f * E0 * (d0 * s - 10.f * s1);
}

// ---------------------------------------------------------------------------
// Weight / table prep (duplicate each weight into both f32x2 lanes)
// ---------------------------------------------------------------------------
__device__ __forceinline__ u64 dupf(float v) {
    u64 u = (u64)__float_as_uint(v);
    return u | (u << 32);
}

__global__ void prep_kernel(const float* __restrict__ f0,
                            const float* __restrict__ fr,
                            const float* __restrict__ actw) {
    int idx = blockIdx.x * 256 + threadIdx.x;
    if (idx < 3 * WSZ) {
        int co = idx & 63;
        int r  = idx >> 6;
        int kx = r % 5; r /= 5;
        int ky = r % 5; r /= 5;
        int ci = r & 63;
        int l  = r >> 6;
        // fwd: wfd[l][ci][ky][kx][co] = fr[l][co][ci][ky][kx]
        g_wfd[idx] = dupf(fr[(((l * 64 + co) * 64 + ci) * 25) + ky * 5 + kx]);
        // bwd (conv_t as zero-padded corr): wbd[l][a][ky][kx][b] = fr[l][a][b][4-ky][4-kx]
        g_wbd[idx] = dupf(fr[(((l * 64 + ci) * 64 + co) * 25) + (4 - ky) * 5 + (4 - kx)]);
    }
    if (idx < 1600) {
        int co = idx & 63;
        int r  = idx >> 6;
        int kx = r % 5, ky = r / 5;
        g_w0d[idx] = dupf(f0[co * 25 + ky * 5 + kx]);     // [ky][kx][co]
        int a = idx / 25, q = idx % 25;
        int u = q / 5, v = q % 5;
        g_w0b[idx] = f0[a * 25 + (4 - u) * 5 + (4 - v)];  // [a][u][v], flipped
    }
    if (idx < 4 * 64 * 80) {
        int q  = (idx % 80) - 8;
        int lc = idx / 80;
        g_actp[idx] = (q >= 0 && q < 63) ? actw[lc * 63 + q] : 0.f;
    }
}

// ---------------------------------------------------------------------------
// Main conv kernel. Tile 32x8 px, 256 threads; thread = 8 px (4 row-pairs)
// x 8 co, accumulated as 32 packed f32x2 (fma.rn.f32x2 -> 2x fp32 rate).
// Weights: lane-duplicated [ci][uv][co] -> warp-uniform LDG.128 of packed ops.
// FWD: replication pad, +bias, store conv (tout if STORE_T) and act (out).
// BWD: zero pad, epilogue gate by act_grad(tg), store to out.
// ---------------------------------------------------------------------------
template <bool BWD, int NCI, bool STORE_T>
__global__ __launch_bounds__(256, 2)
void conv_kernel(const float* __restrict__ in, float inscale,
                 const u64* __restrict__ w,
                 const float* __restrict__ bias,
                 const float* __restrict__ actp,
                 const float* __restrict__ tg,
                 float* __restrict__ tout,
                 float* __restrict__ out) {
    __shared__ float s_act[64 * 80];
    __shared__ float s_in[12 * 36];
    const int tid = threadIdx.x;
    const int x   = tid & 31;
    const int wid = tid >> 5;                  // co octet
    const int n   = blockIdx.z;
    const int tx0 = blockIdx.x * 32, ty0 = blockIdx.y * 8;

    for (int i = tid; i < 64 * 80; i += 256) s_act[i] = actp[i];

    u64 acc[32];
#pragma unroll
    for (int i = 0; i < 32; i++) acc[i] = 0ull;

    for (int ci = 0; ci < NCI; ci++) {
        __syncthreads();                        // also covers s_act on first iter
        const float* ip = in + ((size_t)(n * NCI + ci)) * HW;
        for (int i = tid; i < 432; i += 256) {
            int py = i / 36, px = i - py * 36;
            int gy = ty0 + py - 2, gx = tx0 + px - 2;
            float v;
            if (BWD) {
                v = (gy >= 0 && gy < 128 && gx >= 0 && gx < 128) ? ip[gy * 128 + gx] : 0.f;
            } else {
                gy = min(max(gy, 0), 127);
                gx = min(max(gx, 0), 127);
                v = ip[gy * 128 + gx] * inscale;
            }
            s_in[i] = v;
        }
        __syncthreads();
        const u64* wp = w + ci * 1600 + wid * 8;
#pragma unroll
        for (int u = 0; u < 5; u++) {
#pragma unroll
            for (int v = 0; v < 5; v++) {
                const ulonglong2* wq = reinterpret_cast<const ulonglong2*>(wp + (u * 5 + v) * 64);
                ulonglong2 wA = __ldg(wq);
                ulonglong2 wB = __ldg(wq + 1);
                ulonglong2 wC = __ldg(wq + 2);
                ulonglong2 wD = __ldg(wq + 3);
                u64 ivp[4];
#pragma unroll
                for (int p = 0; p < 4; p++)
                    ivp[p] = pk2(s_in[(2 * p     + u) * 36 + x + v],
                                 s_in[(2 * p + 1 + u) * 36 + x + v]);
#pragma unroll
                for (int p = 0; p < 4; p++) {
                    fma2(acc[p * 8 + 0], ivp[p], wA.x);
                    fma2(acc[p * 8 + 1], ivp[p], wA.y);
                    fma2(acc[p * 8 + 2], ivp[p], wB.x);
                    fma2(acc[p * 8 + 3], ivp[p], wB.y);
                    fma2(acc[p * 8 + 4], ivp[p], wC.x);
                    fma2(acc[p * 8 + 5], ivp[p], wC.y);
                    fma2(acc[p * 8 + 6], ivp[p], wD.x);
                    fma2(acc[p * 8 + 7], ivp[p], wD.y);
                }
            }
        }
    }

    // Epilogue
#pragma unroll
    for (int c = 0; c < 8; c++) {
        const int co = wid * 8 + c;
        const float* wrow = &s_act[co * 80 + 8];
        const float b = BWD ? 0.f : bias[co];
        size_t base = ((size_t)(n * 64 + co)) * HW + (size_t)ty0 * 128 + tx0 + x;
#pragma unroll
        for (int p = 0; p < 4; p++) {
            float2 vv = upk(acc[p * 8 + c]);
            size_t i0 = base + (size_t)(2 * p) * 128;
            size_t i1 = i0 + 128;
            float v0 = vv.x + b;
            float v1 = vv.y + b;
            if (BWD) {
                out[i0] = v0 * act_grad(tg[i0], wrow);
                out[i1] = v1 * act_grad(tg[i1], wrow);
            } else {
                if (STORE_T) { tout[i0] = v0; tout[i1] = v1; }
                out[i0] = act_fwd(v0, wrow);
                out[i1] = act_fwd(v1, wrow);
            }
        }
    }
}

// ---------------------------------------------------------------------------
// Final: r = crop(conv_t(in, f0)) (64->1, zero pad), out = x - r/255 - e^lam*(x-y)
// ci chunked by 4.
// ---------------------------------------------------------------------------
__global__ __launch_bounds__(256)
void final_kernel(const float* __restrict__ in,
                  const float* __restrict__ xin,
                  const float* __restrict__ yin,
                  const float* __restrict__ lam,
                  float* __restrict__ out) {
    __shared__ float s_w[1600];
    __shared__ float s_in[4 * 432];
    const int tid = threadIdx.x;
    const int x   = tid & 31;
    const int yy  = tid >> 5;
    const int n   = blockIdx.z;
    const int tx0 = blockIdx.x * 32, ty0 = blockIdx.y * 8;

    for (int i = tid; i < 1600; i += 256) s_w[i] = g_w0b[i];

    float acc = 0.f;
    for (int c0 = 0; c0 < 64; c0 += 4) {
        __syncthreads();
        for (int i = tid; i < 4 * 432; i += 256) {
            int cc = i / 432, j = i - cc * 432;
            int py = j / 36, px = j - py * 36;
            int gy = ty0 + py - 2, gx = tx0 + px - 2;
            const float* ip = in + ((size_t)(n * 64 + c0 + cc)) * HW;
            s_in[i] = (gy >= 0 && gy < 128 && gx >= 0 && gx < 128) ? ip[gy * 128 + gx] : 0.f;
        }
        __syncthreads();
#pragma unroll
        for (int cc = 0; cc < 4; cc++) {
            const float* wp  = &s_w[(c0 + cc) * 25];
            const float* pin = s_in + cc * 432;
#pragma unroll
            for (int u = 0; u < 5; u++)
#pragma unroll
                for (int v = 0; v < 5; v++)
                    acc += pin[(yy + u) * 36 + x + v] * wp[u * 5 + v];
        }
    }
    size_t idx = (size_t)n * HW + (size_t)(ty0 + yy) * 128 + tx0 + x;
    float xv = xin[idx], yv = yin[idx];
    float el = __expf(lam[0]);
    out[idx] = xv - acc * (1.f / 255.f) - el * (xv - yv);
}

// ---------------------------------------------------------------------------
// Launch
// ---------------------------------------------------------------------------
extern "C" void kernel_launch(void* const* d_in, const int* in_sizes, int n_in,
                              void* d_out, int out_size) {
    const float *x = nullptr, *y = nullptr, *lam = nullptr, *f0 = nullptr,
                *fr = nullptr, *bias = nullptr, *actw = nullptr;
    for (int i = 0; i < n_in; i++) {
        const float* p = (const float*)d_in[i];
        switch (in_sizes[i]) {
            case 65536: if (!x) x = p; else y = p; break;   // x first, y second (metadata order)
            case 1:      lam  = p; break;
            case 1600:   f0   = p; break;
            case 307200: fr   = p; break;
            case 256:    bias = p; break;
            case 16128:  actw = p; break;
            default: break;
        }
    }

    void *pA, *pB, *pT, *pwf, *pwb, *pw0, *pact;
    cudaGetSymbolAddress(&pA, g_A);
    cudaGetSymbolAddress(&pB, g_B);
    cudaGetSymbolAddress(&pT, g_T);
    cudaGetSymbolAddress(&pwf, g_wfd);
    cudaGetSymbolAddress(&pwb, g_wbd);
    cudaGetSymbolAddress(&pw0, g_w0d);
    cudaGetSymbolAddress(&pact, g_actp);
    float* A   = (float*)pA;
    float* B   = (float*)pB;
    float* T   = (float*)pT;
    u64*   wf  = (u64*)pwf;
    u64*   wb  = (u64*)pwb;
    u64*   w0  = (u64*)pw0;
    float* act = (float*)pact;

    dim3 grid(4, 16, 4), blk(256);

    prep_kernel<<<1200, 256>>>(f0, fr, actw);

    // forward: conv0 (1->64, x255) then layers 1..3 (t3 never read -> no store)
    conv_kernel<false, 1,  true ><<<grid, blk>>>(x, 255.f, w0,           bias,       act,            nullptr,          T,                A);
    conv_kernel<false, 64, true ><<<grid, blk>>>(A, 1.f,   wf,           bias + 64,  act + 5120,     nullptr,          T + (size_t)NCHW, B);
    conv_kernel<false, 64, true ><<<grid, blk>>>(B, 1.f,   wf + WSZ,     bias + 128, act + 2 * 5120, nullptr,          T + 2ull * NCHW,  A);
    conv_kernel<false, 64, false><<<grid, blk>>>(A, 1.f,   wf + 2 * WSZ, bias + 192, act + 3 * 5120, nullptr,          nullptr,          B);

    // backward: convT(l) with act_grad(t_{l-1}) gate fused in epilogue
    conv_kernel<true, 64, false><<<grid, blk>>>(B, 1.f, wb + 2 * WSZ, nullptr, act + 2 * 5120, T + 2ull * NCHW,  nullptr, A);
    conv_kernel<true, 64, false><<<grid, blk>>>(A, 1.f, wb + WSZ,     nullptr, act + 5120,     T + (size_t)NCHW, nullptr, B);
    conv_kernel<true, 64, false><<<grid, blk>>>(B, 1.f, wb,           nullptr, act,            T,                nullptr, A);

    // final convT (64->1) + combine
    final_kernel<<<grid, blk>>>(A, x, y, lam, (float*)d_out);
}

// round 11
// speedup vs baseline: 1.4839x; 1.4797x over previous
#include <cuda_runtime.h>
#include <cuda_bf16.h>
#include <cstdint>
#include <cstddef>

#define HW 16384
#define NCHW 4194304
#define LWBF 204800            // bf16 per layer-dir weight blob
#define DSMEM 165760           // 63360 (A) + 102400 (B) bytes
typedef uint32_t u32;
typedef __nv_bfloat16 bf;

__device__ bf g_Ah[NCHW], g_Al[NCHW], g_Bh[NCHW], g_Bl[NCHW];
__device__ float g_T[3ull * NCHW];
__device__ bf g_wbf[6 * LWBF];       // [ld6][chunk4][tap25][half2][co64][ci16]
__device__ float g_w0[1600];         // conv0 [uv][co]
__device__ float g_w0b[1600];        // final convT [a][u][v] flipped
__device__ float g_actp[20480];      // [l4][c64][80], data at +8

// ---- helpers -------------------------------------------------------------
__device__ __forceinline__ u32 s2u(const void* p) {
    u32 a; asm("{.reg .u64 t; cvta.to.shared.u64 t,%1; cvt.u32.u64 %0,t;}" : "=r"(a) : "l"(p));
    return a;
}
__device__ __forceinline__ void ldsm4(u32* r, u32 a) {
    asm volatile("ldmatrix.sync.aligned.m8n8.x4.shared.b16 {%0,%1,%2,%3},[%4];"
                 : "=r"(r[0]), "=r"(r[1]), "=r"(r[2]), "=r"(r[3]) : "r"(a));
}
__device__ __forceinline__ void ldsm2(u32* r, u32 a) {
    asm volatile("ldmatrix.sync.aligned.m8n8.x2.shared.b16 {%0,%1},[%2];"
                 : "=r"(r[0]), "=r"(r[1]) : "r"(a));
}
__device__ __forceinline__ void mma16816(float* d, const u32* a, const u32* b) {
    asm volatile("mma.sync.aligned.m16n8k16.row.col.f32.bf16.bf16.f32 "
                 "{%0,%1,%2,%3},{%4,%5,%6,%7},{%8,%9},{%0,%1,%2,%3};"
                 : "+f"(d[0]), "+f"(d[1]), "+f"(d[2]), "+f"(d[3])
                 : "r"(a[0]), "r"(a[1]), "r"(a[2]), "r"(a[3]), "r"(b[0]), "r"(b[1]));
}

// ---- RBF activation, windowed |k|<=6 recurrence (verified R2) ------------
__device__ __forceinline__ float act_fwd(float v, const float* __restrict__ wr) {
    float pf = rintf((v + 310.f) * 0.1f); pf = fminf(fmaxf(pf, 0.f), 62.f);
    float d0 = v + 310.f - 10.f * pf; d0 = fminf(fmaxf(d0, -55.f), 55.f);
    float a = __expf(0.1f * d0), ai = __expf(-0.1f * d0), E0 = __expf(-0.005f * d0 * d0);
    const float* w = wr + (int)pf;
    const float CK[7] = {0.f, 0.60653066f, 0.22313016f, 0.082084999f, 0.030197383f, 0.011108997f, 0.0040867714f};
    float s = w[0], up = 1.f, un = 1.f;
#pragma unroll
    for (int k = 1; k <= 6; k++) { up *= a * CK[k]; un *= ai * CK[k]; s += w[k] * up + w[-k] * un; }
    return E0 * s;
}
__device__ __forceinline__ float act_grad(float v, const float* __restrict__ wr) {
    float pf = rintf((v + 310.f) * 0.1f); pf = fminf(fmaxf(pf, 0.f), 62.f);
    float d0 = v + 310.f - 10.f * pf; d0 = fminf(fmaxf(d0, -55.f), 55.f);
    float a = __expf(0.1f * d0), ai = __expf(-0.1f * d0), E0 = __expf(-0.005f * d0 * d0);
    const float* w = wr + (int)pf;
    const float CK[7] = {0.f, 0.60653066f, 0.22313016f, 0.082084999f, 0.030197383f, 0.011108997f, 0.0040867714f};
    float s = w[0], s1 = 0.f, up = 1.f, un = 1.f;
#pragma unroll
    for (int k = 1; k <= 6; k++) {
        up *= a * CK[k]; un *= ai * CK[k];
        float tp = w[k] * up, tm = w[-k] * un;
        s += tp + tm; s1 += (float)k * (tp - tm);
    }
    return -0.01f * E0 * (d0 * s - 10.f * s1);
}

// ---- prep ----------------------------------------------------------------
__global__ void prep_kernel(const float* __restrict__ f0, const float* __restrict__ fr,
                            const float* __restrict__ actw) {
    int idx = blockIdx.x * 256 + threadIdx.x;
    if (idx < 307200) {
        int co = idx & 63, r = idx >> 6;
        int tap = r % 25; r /= 25;
        int ci = r & 63, l = r >> 6;
        int u = tap / 5, v = tap % 5, flip = (4 - u) * 5 + (4 - v);
        float wf = fr[((l * 64 + co) * 64 + ci) * 25 + tap];
        float wb = fr[((l * 64 + ci) * 64 + co) * 25 + flip];
        int ck = ci >> 4, c16 = ci & 15;
        size_t of = ((((size_t)(l * 4 + ck) * 25 + tap) * 2) * 64 + co) * 16 + c16;
        size_t ob = (((((size_t)(3 + l) * 4 + ck) * 25 + tap) * 2) * 64 + co) * 16 + c16;
        bf fh = __float2bfloat16_rn(wf), bh = __float2bfloat16_rn(wb);
        g_wbf[of] = fh;        g_wbf[of + 1024] = __float2bfloat16_rn(wf - __bfloat162float(fh));
        g_wbf[ob] = bh;        g_wbf[ob + 1024] = __float2bfloat16_rn(wb - __bfloat162float(bh));
    }
    if (idx < 1600) {
        int co = idx & 63, uv = idx >> 6;
        g_w0[uv * 64 + co] = f0[co * 25 + uv];
        int a = idx / 25, q = idx % 25, u = q / 5, v = q % 5;
        g_w0b[a * 25 + q] = f0[a * 25 + (4 - u) * 5 + (4 - v)];
    }
    if (idx < 20480) {
        int q = (idx % 80) - 8, lc = idx / 80;
        g_actp[idx] = (q >= 0 && q < 63) ? actw[lc * 63 + q] : 0.f;
    }
}

// ---- mma.sync conv layer (64->64, bf16 hi/lo x 3 products) ---------------
// CTA: one output row y (128 px x 64 co). Warp: 32px x 32co.
// smem: A [half2][row5][x132][ci pad24] bf16 (63360B) ; B [tap25][half2][co64][ci16] (102400B)
template <bool BWD, bool STORE_T>
__global__ __launch_bounds__(256)
void mma_conv(const bf* __restrict__ inH, const bf* __restrict__ inL,
              const bf* __restrict__ wbf, const float* __restrict__ bias,
              const float* __restrict__ actp, const float* __restrict__ tg,
              float* __restrict__ tout, bf* __restrict__ outH, bf* __restrict__ outL) {
    extern __shared__ __align__(16) char smem[];
    bf* sA = (bf*)smem;
    const int tid = threadIdx.x, w = tid >> 5, lane = tid & 31;
    const int n = blockIdx.z, y = blockIdx.x;
    const int x0 = (w & 3) * 32, co0 = (w >> 2) * 32;

    const u32 base = s2u(smem);
    u32 aSt[2][2], bSt[2][4];
#pragma unroll
    for (int h = 0; h < 2; h++) {
#pragma unroll
        for (int mt = 0; mt < 2; mt++)
            aSt[h][mt] = base + h * 31680 +
                (((x0 + 16 * mt + (lane & 15)) * 24 + ((lane >> 4) << 3)) << 1);
#pragma unroll
        for (int nt = 0; nt < 4; nt++)
            bSt[h][nt] = base + 63360 + h * 2048 +
                (((co0 + 8 * nt + (lane & 7)) * 16 + (((lane >> 3) & 1) << 3)) << 1);
    }

    float acc[2][4][4];
#pragma unroll
    for (int i = 0; i < 2; i++)
#pragma unroll
        for (int j = 0; j < 4; j++)
#pragma unroll
            for (int k = 0; k < 4; k++) acc[i][j][k] = 0.f;

    for (int ck = 0; ck < 4; ck++) {
        __syncthreads();
        // stage A: 5 rows x 132 x x 16 ci x 2 halves
        for (int i = tid; i < 21120; i += 256) {
            int x = i % 132, j = i / 132;
            int c = j & 15; j >>= 4;
            int r = j % 5, h = j / 5;
            int gy = y + r - 2, gx = x - 2;
            const bf* src = (h ? inL : inH) + ((size_t)(n * 64 + ck * 16 + c)) * HW;
            bf v;
            if (BWD) {
                v = (gy >= 0 && gy < 128 && gx >= 0 && gx < 128)
                    ? src[gy * 128 + gx] : __float2bfloat16_rn(0.f);
            } else {
                int cy = min(max(gy, 0), 127), cx = min(max(gx, 0), 127);
                v = src[cy * 128 + cx];
            }
            sA[h * 15840 + (r * 132 + x) * 24 + c] = v;
        }
        // stage B: 6400 x 16B
        {
            const uint4* bs = (const uint4*)(wbf + (size_t)ck * 51200);
            uint4* bd = (uint4*)(smem + 63360);
            for (int i = tid; i < 6400; i += 256) bd[i] = bs[i];
        }
        __syncthreads();
#pragma unroll 1
        for (int tap = 0; tap < 25; tap++) {
            int u = tap / 5, v = tap - 5 * u;
            u32 sh = (u32)(u * 132 + v) * 48;
            u32 Ah0[4], Ah1[4], Al0[4], Al1[4];
            ldsm4(Ah0, aSt[0][0] + sh); ldsm4(Ah1, aSt[0][1] + sh);
            ldsm4(Al0, aSt[1][0] + sh); ldsm4(Al1, aSt[1][1] + sh);
            u32 bt = (u32)tap * 4096;
            u32 Bh[4][2], Bl[4][2];
#pragma unroll
            for (int nt = 0; nt < 4; nt++) {
                ldsm2(Bh[nt], bSt[0][nt] + bt);
                ldsm2(Bl[nt], bSt[1][nt] + bt);
            }
#pragma unroll
            for (int nt = 0; nt < 4; nt++) {
                mma16816(acc[0][nt], Ah0, Bh[nt]);
                mma16816(acc[0][nt], Ah0, Bl[nt]);
                mma16816(acc[0][nt], Al0, Bh[nt]);
                mma16816(acc[1][nt], Ah1, Bh[nt]);
                mma16816(acc[1][nt], Ah1, Bl[nt]);
                mma16816(acc[1][nt], Al1, Bh[nt]);
            }
        }
    }

    // epilogue: act table into smem (reuse), then activate/gate + split-store
    __syncthreads();
    float* sF = (float*)smem;
    for (int i = tid; i < 5120; i += 256) sF[i] = actp[i];
    __syncthreads();

    const int g = lane >> 2, t2 = (lane & 3) * 2;
#pragma unroll
    for (int mt = 0; mt < 2; mt++)
#pragma unroll
        for (int nt = 0; nt < 4; nt++) {
            const float* d = acc[mt][nt];
            int pxb = x0 + 16 * mt + g, cb = co0 + 8 * nt + t2;
#pragma unroll
            for (int e = 0; e < 4; e++) {
                int px = pxb + ((e >> 1) << 3);
                int co = cb + (e & 1);
                size_t idx = ((size_t)(n * 64 + co)) * HW + (size_t)y * 128 + px;
                const float* wr = sF + co * 80 + 8;
                float val = d[e], r;
                if (BWD) {
                    r = val * act_grad(tg[idx], wr);
                } else {
                    val += bias[co];
                    if (STORE_T) tout[idx] = val;
                    r = act_fwd(val, wr);
                }
                bf hi = __float2bfloat16_rn(r);
                outH[idx] = hi;
                outL[idx] = __float2bfloat16_rn(r - __bfloat162float(hi));
            }
        }
}

// ---- conv0: 1->64 scalar (rep-pad, x255, bias, t0, act -> hi/lo) ---------
__global__ __launch_bounds__(256)
void conv0_kernel(const float* __restrict__ x, const float* __restrict__ bias,
                  float* __restrict__ tout, bf* __restrict__ outH, bf* __restrict__ outL) {
    __shared__ float s_w[1600], s_act[5120], s_in[432];
    const int tid = threadIdx.x, xx = tid & 31, wid = tid >> 5;
    const int n = blockIdx.z, tx0 = blockIdx.x * 32, ty0 = blockIdx.y * 8;
    for (int i = tid; i < 1600; i += 256) s_w[i] = g_w0[i];
    for (int i = tid; i < 5120; i += 256) s_act[i] = g_actp[i];
    const float* ip = x + (size_t)n * HW;
    for (int i = tid; i < 432; i += 256) {
        int py = i / 36, px = i - py * 36;
        int gy = min(max(ty0 + py - 2, 0), 127), gx = min(max(tx0 + px - 2, 0), 127);
        s_in[i] = ip[gy * 128 + gx] * 255.f;
    }
    __syncthreads();
    float acc[64];
#pragma unroll
    for (int i = 0; i < 64; i++) acc[i] = 0.f;
#pragma unroll
    for (int u = 0; u < 5; u++)
#pragma unroll
        for (int v = 0; v < 5; v++) {
            const float4* wq = (const float4*)&s_w[(u * 5 + v) * 64 + wid * 8];
            float4 wa = wq[0], wb = wq[1];
#pragma unroll
            for (int yy = 0; yy < 8; yy++) {
                float iv = s_in[(yy + u) * 36 + xx + v];
                acc[yy * 8 + 0] += iv * wa.x;  acc[yy * 8 + 1] += iv * wa.y;
                acc[yy * 8 + 2] += iv * wa.z;  acc[yy * 8 + 3] += iv * wa.w;
                acc[yy * 8 + 4] += iv * wb.x;  acc[yy * 8 + 5] += iv * wb.y;
                acc[yy * 8 + 6] += iv * wb.z;  acc[yy * 8 + 7] += iv * wb.w;
            }
        }
#pragma unroll
    for (int c = 0; c < 8; c++) {
        int co = wid * 8 + c;
        const float* wr = &s_act[co * 80 + 8];
        float b = bias[co];
        size_t basei = ((size_t)(n * 64 + co)) * HW + (size_t)ty0 * 128 + tx0 + xx;
#pragma unroll
        for (int yy = 0; yy < 8; yy++) {
            size_t idx = basei + (size_t)yy * 128;
            float v = acc[yy * 8 + c] + b;
            tout[idx] = v;
            float a = act_fwd(v, wr);
            bf hi = __float2bfloat16_rn(a);
            outH[idx] = hi;
            outL[idx] = __float2bfloat16_rn(a - __bfloat162float(hi));
        }
    }
}

// ---- final: crop(conv_t(in, f0)) 64->1 + combine -------------------------
__global__ __launch_bounds__(256)
void final_kernel(const bf* __restrict__ inH, const bf* __restrict__ inL,
                  const float* __restrict__ xin, const float* __restrict__ yin,
                  const float* __restrict__ lam, float* __restrict__ out) {
    __shared__ float s_w[1600], s_in[4 * 432];
    const int tid = threadIdx.x, x = tid & 31, yy = tid >> 5;
    const int n = blockIdx.z, tx0 = blockIdx.x * 32, ty0 = blockIdx.y * 8;
    for (int i = tid; i < 1600; i += 256) s_w[i] = g_w0b[i];
    float acc = 0.f;
    for (int c0 = 0; c0 < 64; c0 += 4) {
        __syncthreads();
        for (int i = tid; i < 4 * 432; i += 256) {
            int cc = i / 432, j = i - cc * 432;
            int py = j / 36, px = j - py * 36;
            int gy = ty0 + py - 2, gx = tx0 + px - 2;
            size_t o = ((size_t)(n * 64 + c0 + cc)) * HW + gy * 128 + gx;
            s_in[i] = (gy >= 0 && gy < 128 && gx >= 0 && gx < 128)
                      ? (__bfloat162float(inH[o]) + __bfloat162float(inL[o])) : 0.f;
        }
        __syncthreads();
#pragma unroll
        for (int cc = 0; cc < 4; cc++) {
            const float* wp = &s_w[(c0 + cc) * 25];
            const float* pin = s_in + cc * 432;
#pragma unroll
            for (int u = 0; u < 5; u++)
#pragma unroll
                for (int v = 0; v < 5; v++)
                    acc += pin[(yy + u) * 36 + x + v] * wp[u * 5 + v];
        }
    }
    size_t idx = (size_t)n * HW + (size_t)(ty0 + yy) * 128 + tx0 + x;
    float xv = xin[idx], yv = yin[idx];
    out[idx] = xv - acc * (1.f / 255.f) - __expf(lam[0]) * (xv - yv);
}

// ---- launch --------------------------------------------------------------
extern "C" void kernel_launch(void* const* d_in, const int* in_sizes, int n_in,
                              void* d_out, int out_size) {
    const float *x = nullptr, *y = nullptr, *lam = nullptr, *f0 = nullptr,
                *fr = nullptr, *bias = nullptr, *actw = nullptr;
    for (int i = 0; i < n_in; i++) {
        const float* p = (const float*)d_in[i];
        switch (in_sizes[i]) {
            case 65536: if (!x) x = p; else y = p; break;
            case 1: lam = p; break;
            case 1600: f0 = p; break;
            case 307200: fr = p; break;
            case 256: bias = p; break;
            case 16128: actw = p; break;
            default: break;
        }
    }
    void *pAh, *pAl, *pBh, *pBl, *pT, *pW, *pact;
    cudaGetSymbolAddress(&pAh, g_Ah); cudaGetSymbolAddress(&pAl, g_Al);
    cudaGetSymbolAddress(&pBh, g_Bh); cudaGetSymbolAddress(&pBl, g_Bl);
    cudaGetSymbolAddress(&pT, g_T);   cudaGetSymbolAddress(&pW, g_wbf);
    cudaGetSymbolAddress(&pact, g_actp);
    bf *Ah = (bf*)pAh, *Al = (bf*)pAl, *Bh = (bf*)pBh, *Bl = (bf*)pBl;
    float *T = (float*)pT, *act = (float*)pact;
    bf *W = (bf*)pW;

    cudaFuncSetAttribute(mma_conv<false, true >, cudaFuncAttributeMaxDynamicSharedMemorySize, DSMEM);
    cudaFuncSetAttribute(mma_conv<false, false>, cudaFuncAttributeMaxDynamicSharedMemorySize, DSMEM);
    cudaFuncSetAttribute(mma_conv<true,  false>, cudaFuncAttributeMaxDynamicSharedMemorySize, DSMEM);

    dim3 gs(4, 16, 4), gm(128, 1, 4), blk(256);
    prep_kernel<<<1200, 256>>>(f0, fr, actw);
    conv0_kernel<<<gs, blk>>>(x, bias, T, Ah, Al);
    // forward layers 1..3 (weights ld0..2)
    mma_conv<false, true ><<<gm, blk, DSMEM>>>(Ah, Al, W,            bias + 64,  act + 5120,     nullptr, T + (size_t)NCHW, Bh, Bl);
    mma_conv<false, true ><<<gm, blk, DSMEM>>>(Bh, Bl, W + LWBF,     bias + 128, act + 2 * 5120, nullptr, T + 2ull * NCHW,  Ah, Al);
    mma_conv<false, false><<<gm, blk, DSMEM>>>(Ah, Al, W + 2 * LWBF, bias + 192, act + 3 * 5120, nullptr, nullptr,          Bh, Bl);
    // backward: convT(w3) gate t2, convT(w2) gate t1, convT(w1) gate t0
    mma_conv<true, false><<<gm, blk, DSMEM>>>(Bh, Bl, W + 5 * LWBF, nullptr, act + 2 * 5120, T + 2ull * NCHW,  nullptr, Ah, Al);
    mma_conv<true, false><<<gm, blk, DSMEM>>>(Ah, Al, W + 4 * LWBF, nullptr, act + 5120,     T + (size_t)NCHW, nullptr, Bh, Bl);
    mma_conv<true, false><<<gm, blk, DSMEM>>>(Bh, Bl, W + 3 * LWBF, nullptr, act,            T,                nullptr, Ah, Al);
    final_kernel<<<gs, blk>>>(Ah, Al, x, y, lam, (float*)d_out);
}

// round 12
// speedup vs baseline: 3.0086x; 2.0275x over previous
#include <cuda_runtime.h>
#include <cuda_bf16.h>
#include <cstdint>
#include <cstddef>

#define HW 16384
#define NCHW 4194304
#define LWBF 204800            // bf16 per layer-dir weight blob
#define BBASE 63360            // A slab bytes (2 halves x 5 x 132 x 24ci x 2B)
#define DSMEM 104320           // 63360 (A) + 40960 (B group: 10 taps)
typedef uint32_t u32;
typedef __nv_bfloat16 bf;

// channel-last [n][y][x][c] hi/lo activation tensors
__device__ bf g_Ah[NCHW], g_Al[NCHW], g_Bh[NCHW], g_Bl[NCHW];
__device__ float g_T[3ull * NCHW];   // t0..t2, channel-last fp32
__device__ bf g_wbf[6 * LWBF];       // [ld6][chunk4][tap25][half2][co64][ci16]
__device__ float g_w0[1600];         // conv0 [uv][co]
__device__ float g_w0b[1600];        // final convT [a][u][v] flipped
__device__ float g_actp[20480];      // [l4][c64][80], data at +8

// ---- helpers -------------------------------------------------------------
__device__ __forceinline__ u32 s2u(const void* p) {
    u32 a; asm("{.reg .u64 t; cvta.to.shared.u64 t,%1; cvt.u32.u64 %0,t;}" : "=r"(a) : "l"(p));
    return a;
}
__device__ __forceinline__ void ldsm4(u32* r, u32 a) {
    asm volatile("ldmatrix.sync.aligned.m8n8.x4.shared.b16 {%0,%1,%2,%3},[%4];"
                 : "=r"(r[0]), "=r"(r[1]), "=r"(r[2]), "=r"(r[3]) : "r"(a));
}
__device__ __forceinline__ void ldsm2(u32* r, u32 a) {
    asm volatile("ldmatrix.sync.aligned.m8n8.x2.shared.b16 {%0,%1},[%2];"
                 : "=r"(r[0]), "=r"(r[1]) : "r"(a));
}
__device__ __forceinline__ void mma16816(float* d, const u32* a, const u32* b) {
    asm volatile("mma.sync.aligned.m16n8k16.row.col.f32.bf16.bf16.f32 "
                 "{%0,%1,%2,%3},{%4,%5,%6,%7},{%8,%9},{%0,%1,%2,%3};"
                 : "+f"(d[0]), "+f"(d[1]), "+f"(d[2]), "+f"(d[3])
                 : "r"(a[0]), "r"(a[1]), "r"(a[2]), "r"(a[3]), "r"(b[0]), "r"(b[1]));
}

// ---- RBF activation, windowed |k|<=6 recurrence (verified R2) ------------
__device__ __forceinline__ float act_fwd(float v, const float* __restrict__ wr) {
    float pf = rintf((v + 310.f) * 0.1f); pf = fminf(fmaxf(pf, 0.f), 62.f);
    float d0 = v + 310.f - 10.f * pf; d0 = fminf(fmaxf(d0, -55.f), 55.f);
    float a = __expf(0.1f * d0), ai = __expf(-0.1f * d0), E0 = __expf(-0.005f * d0 * d0);
    const float* w = wr + (int)pf;
    const float CK[7] = {0.f, 0.60653066f, 0.22313016f, 0.082084999f, 0.030197383f, 0.011108997f, 0.0040867714f};
    float s = w[0], up = 1.f, un = 1.f;
#pragma unroll
    for (int k = 1; k <= 6; k++) { up *= a * CK[k]; un *= ai * CK[k]; s += w[k] * up + w[-k] * un; }
    return E0 * s;
}
__device__ __forceinline__ float act_grad(float v, const float* __restrict__ wr) {
    float pf = rintf((v + 310.f) * 0.1f); pf = fminf(fmaxf(pf, 0.f), 62.f);
    float d0 = v + 310.f - 10.f * pf; d0 = fminf(fmaxf(d0, -55.f), 55.f);
    float a = __expf(0.1f * d0), ai = __expf(-0.1f * d0), E0 = __expf(-0.005f * d0 * d0);
    const float* w = wr + (int)pf;
    const float CK[7] = {0.f, 0.60653066f, 0.22313016f, 0.082084999f, 0.030197383f, 0.011108997f, 0.0040867714f};
    float s = w[0], s1 = 0.f, up = 1.f, un = 1.f;
#pragma unroll
    for (int k = 1; k <= 6; k++) {
        up *= a * CK[k]; un *= ai * CK[k];
        float tp = w[k] * up, tm = w[-k] * un;
        s += tp + tm; s1 += (float)k * (tp - tm);
    }
    return -0.01f * E0 * (d0 * s - 10.f * s1);
}

// ---- prep ----------------------------------------------------------------
__global__ void prep_kernel(const float* __restrict__ f0, const float* __restrict__ fr,
                            const float* __restrict__ actw) {
    int idx = blockIdx.x * 256 + threadIdx.x;
    if (idx < 307200) {
        int co = idx & 63, r = idx >> 6;
        int tap = r % 25; r /= 25;
        int ci = r & 63, l = r >> 6;
        int u = tap / 5, v = tap % 5, flip = (4 - u) * 5 + (4 - v);
        float wf = fr[((l * 64 + co) * 64 + ci) * 25 + tap];
        float wb = fr[((l * 64 + ci) * 64 + co) * 25 + flip];
        int ck = ci >> 4, c16 = ci & 15;
        size_t of = ((((size_t)(l * 4 + ck) * 25 + tap) * 2) * 64 + co) * 16 + c16;
        size_t ob = (((((size_t)(3 + l) * 4 + ck) * 25 + tap) * 2) * 64 + co) * 16 + c16;
        bf fh = __float2bfloat16_rn(wf), bh = __float2bfloat16_rn(wb);
        g_wbf[of] = fh;        g_wbf[of + 1024] = __float2bfloat16_rn(wf - __bfloat162float(fh));
        g_wbf[ob] = bh;        g_wbf[ob + 1024] = __float2bfloat16_rn(wb - __bfloat162float(bh));
    }
    if (idx < 1600) {
        int co = idx & 63, uv = idx >> 6;
        g_w0[uv * 64 + co] = f0[co * 25 + uv];
        int a = idx / 25, q = idx % 25, u = q / 5, v = q % 5;
        g_w0b[a * 25 + q] = f0[a * 25 + (4 - u) * 5 + (4 - v)];
    }
    if (idx < 20480) {
        int q = (idx % 80) - 8, lc = idx / 80;
        g_actp[idx] = (q >= 0 && q < 63) ? actw[lc * 63 + q] : 0.f;
    }
}

// ---- mma.sync conv layer (64->64, bf16 hi/lo x 3 products) ---------------
// CTA: one output row y (128 px x 64 co). Warp: 32px x 32co. 2 CTAs/SM.
// A smem: [half2][row5][x132][ci pad24] (63360B), staged as uint4 from
// channel-last gmem. B smem: tap-groups of 10 (40960B).
template <bool BWD, bool STORE_T>
__global__ __launch_bounds__(256, 2)
void mma_conv(const bf* __restrict__ inH, const bf* __restrict__ inL,
              const bf* __restrict__ wbf, const float* __restrict__ bias,
              const float* __restrict__ actp, const float* __restrict__ tg,
              float* __restrict__ tout, bf* __restrict__ outH, bf* __restrict__ outL) {
    extern __shared__ __align__(16) char smem[];
    const int tid = threadIdx.x, w = tid >> 5, lane = tid & 31;
    const int n = blockIdx.z, y = blockIdx.x;
    const int x0 = (w & 3) * 32, co0 = (w >> 2) * 32;

    const u32 base = s2u(smem);
    u32 aSt[2][2], bSt[2][4];
#pragma unroll
    for (int h = 0; h < 2; h++) {
#pragma unroll
        for (int mt = 0; mt < 2; mt++)
            aSt[h][mt] = base + h * 31680 +
                (((x0 + 16 * mt + (lane & 15)) * 24 + ((lane >> 4) << 3)) << 1);
#pragma unroll
        for (int nt = 0; nt < 4; nt++)
            bSt[h][nt] = base + BBASE + h * 2048 +
                (((co0 + 8 * nt + (lane & 7)) * 16 + (((lane >> 3) & 1) << 3)) << 1);
    }

    float acc[2][4][4];
#pragma unroll
    for (int i = 0; i < 2; i++)
#pragma unroll
        for (int j = 0; j < 4; j++)
#pragma unroll
            for (int k = 0; k < 4; k++) acc[i][j][k] = 0.f;

    const size_t imgbase = (size_t)n * HW * 64;

    for (int ck = 0; ck < 4; ck++) {
        for (int g = 0; g < 3; g++) {
            const int t0 = g * 10, ngt = (g == 2) ? 5 : 10;
            __syncthreads();
            if (g == 0) {
                // stage A: 2640 uint4 copies (2 halves x 660 positions x 2)
                const bf* pH = inH + imgbase + ck * 16;
                const bf* pL = inL + imgbase + ck * 16;
                for (int i = tid; i < 2640; i += 256) {
                    int q = i & 1, p = i >> 1;
                    int h = (p >= 660) ? 1 : 0;
                    int pos = p - h * 660;
                    int r = pos / 132, x = pos - r * 132;
                    int gy = y + r - 2, gx = x - 2;
                    const bf* src = h ? pL : pH;
                    uint4 v;
                    if (BWD) {
                        if (gy >= 0 && gy < 128 && gx >= 0 && gx < 128)
                            v = *(const uint4*)(src + (size_t)(gy * 128 + gx) * 64 + q * 8);
                        else v = make_uint4(0, 0, 0, 0);
                    } else {
                        int cy = min(max(gy, 0), 127), cx = min(max(gx, 0), 127);
                        v = *(const uint4*)(src + (size_t)(cy * 128 + cx) * 64 + q * 8);
                    }
                    *(uint4*)(smem + h * 31680 + pos * 48 + q * 16) = v;
                }
            }
            // stage B group (ngt taps x 4096B)
            {
                const uint4* bs = (const uint4*)(wbf + (size_t)ck * 51200 + (size_t)t0 * 2048);
                uint4* bd = (uint4*)(smem + BBASE);
                const int nb = ngt * 256;
                for (int i = tid; i < nb; i += 256) bd[i] = bs[i];
            }
            __syncthreads();
#pragma unroll 1
            for (int tl = 0; tl < ngt; tl++) {
                int tap = t0 + tl;
                int u = tap / 5, v = tap - 5 * u;
                u32 sh = (u32)(u * 132 + v) * 48;
                u32 Ah0[4], Ah1[4], Al0[4], Al1[4];
                ldsm4(Ah0, aSt[0][0] + sh); ldsm4(Ah1, aSt[0][1] + sh);
                ldsm4(Al0, aSt[1][0] + sh); ldsm4(Al1, aSt[1][1] + sh);
                u32 bt = (u32)tl * 4096;
                u32 Bh[4][2], Bl[4][2];
#pragma unroll
                for (int nt = 0; nt < 4; nt++) {
                    ldsm2(Bh[nt], bSt[0][nt] + bt);
                    ldsm2(Bl[nt], bSt[1][nt] + bt);
                }
#pragma unroll
                for (int nt = 0; nt < 4; nt++) {
                    mma16816(acc[0][nt], Ah0, Bh[nt]);
                    mma16816(acc[0][nt], Ah0, Bl[nt]);
                    mma16816(acc[0][nt], Al0, Bh[nt]);
                    mma16816(acc[1][nt], Ah1, Bh[nt]);
                    mma16816(acc[1][nt], Ah1, Bl[nt]);
                    mma16816(acc[1][nt], Al1, Bh[nt]);
                }
            }
        }
    }

    // epilogue: act table into smem, then activate/gate + channel-last stores
    __syncthreads();
    float* sF = (float*)smem;
    for (int i = tid; i < 5120; i += 256) sF[i] = actp[i];
    __syncthreads();

    const int g2 = lane >> 2, t2 = (lane & 3) * 2;
#pragma unroll
    for (int mt = 0; mt < 2; mt++)
#pragma unroll
        for (int nt = 0; nt < 4; nt++) {
            const float* d = acc[mt][nt];
            int pxb = x0 + 16 * mt + g2, cb = co0 + 8 * nt + t2;
            const float* wr0 = sF + cb * 80 + 8;
            const float* wr1 = wr0 + 80;
#pragma unroll
            for (int rr = 0; rr < 2; rr++) {
                int px = pxb + rr * 8;
                float v0 = d[rr * 2 + 0], v1 = d[rr * 2 + 1];
                size_t p = ((size_t)n * HW + (size_t)y * 128 + px) * 64 + cb;
                float r0, r1;
                if (BWD) {
                    float2 tv = *(const float2*)(tg + p);
                    r0 = v0 * act_grad(tv.x, wr0);
                    r1 = v1 * act_grad(tv.y, wr1);
                } else {
                    v0 += bias[cb]; v1 += bias[cb + 1];
                    if (STORE_T) *(float2*)(tout + p) = make_float2(v0, v1);
                    r0 = act_fwd(v0, wr0);
                    r1 = act_fwd(v1, wr1);
                }
                bf h0 = __float2bfloat16_rn(r0), h1 = __float2bfloat16_rn(r1);
                __nv_bfloat162 hh; hh.x = h0; hh.y = h1;
                *(__nv_bfloat162*)(outH + p) = hh;
                __nv_bfloat162 ll;
                ll.x = __float2bfloat16_rn(r0 - __bfloat162float(h0));
                ll.y = __float2bfloat16_rn(r1 - __bfloat162float(h1));
                *(__nv_bfloat162*)(outL + p) = ll;
            }
        }
}

// ---- conv0: 1->64 scalar (rep-pad, x255, bias, t0, act), channel-last out
__global__ __launch_bounds__(256)
void conv0_kernel(const float* __restrict__ x, const float* __restrict__ bias,
                  float* __restrict__ tout, bf* __restrict__ outH, bf* __restrict__ outL) {
    __shared__ float s_w[1600], s_act[5120], s_in[432];
    const int tid = threadIdx.x, xx = tid & 31, wid = tid >> 5;
    const int n = blockIdx.z, tx0 = blockIdx.x * 32, ty0 = blockIdx.y * 8;
    for (int i = tid; i < 1600; i += 256) s_w[i] = g_w0[i];
    for (int i = tid; i < 5120; i += 256) s_act[i] = g_actp[i];
    const float* ip = x + (size_t)n * HW;
    for (int i = tid; i < 432; i += 256) {
        int py = i / 36, px = i - py * 36;
        int gy = min(max(ty0 + py - 2, 0), 127), gx = min(max(tx0 + px - 2, 0), 127);
        s_in[i] = ip[gy * 128 + gx] * 255.f;
    }
    __syncthreads();
    float acc[64];
#pragma unroll
    for (int i = 0; i < 64; i++) acc[i] = 0.f;
#pragma unroll
    for (int u = 0; u < 5; u++)
#pragma unroll
        for (int v = 0; v < 5; v++) {
            const float4* wq = (const float4*)&s_w[(u * 5 + v) * 64 + wid * 8];
            float4 wa = wq[0], wb = wq[1];
#pragma unroll
            for (int yy = 0; yy < 8; yy++) {
                float iv = s_in[(yy + u) * 36 + xx + v];
                acc[yy * 8 + 0] += iv * wa.x;  acc[yy * 8 + 1] += iv * wa.y;
                acc[yy * 8 + 2] += iv * wa.z;  acc[yy * 8 + 3] += iv * wa.w;
                acc[yy * 8 + 4] += iv * wb.x;  acc[yy * 8 + 5] += iv * wb.y;
                acc[yy * 8 + 6] += iv * wb.z;  acc[yy * 8 + 7] += iv * wb.w;
            }
        }
#pragma unroll
    for (int c = 0; c < 8; c += 2) {
        int co = wid * 8 + c;
        const float* wr0 = &s_act[co * 80 + 8];
        const float* wr1 = wr0 + 80;
        float b0 = bias[co], b1 = bias[co + 1];
#pragma unroll
        for (int yy = 0; yy < 8; yy++) {
            size_t p = ((size_t)n * HW + (size_t)(ty0 + yy) * 128 + tx0 + xx) * 64 + co;
            float v0 = acc[yy * 8 + c] + b0, v1 = acc[yy * 8 + c + 1] + b1;
            *(float2*)(tout + p) = make_float2(v0, v1);
            float r0 = act_fwd(v0, wr0), r1 = act_fwd(v1, wr1);
            bf h0 = __float2bfloat16_rn(r0), h1 = __float2bfloat16_rn(r1);
            __nv_bfloat162 hh; hh.x = h0; hh.y = h1;
            *(__nv_bfloat162*)(outH + p) = hh;
            __nv_bfloat162 ll;
            ll.x = __float2bfloat16_rn(r0 - __bfloat162float(h0));
            ll.y = __float2bfloat16_rn(r1 - __bfloat162float(h1));
            *(__nv_bfloat162*)(outL + p) = ll;
        }
    }
}

// ---- final: crop(conv_t(in, f0)) 64->1 + combine (channel-last input) ----
__global__ __launch_bounds__(256)
void final_kernel(const bf* __restrict__ inH, const bf* __restrict__ inL,
                  const float* __restrict__ xin, const float* __restrict__ yin,
                  const float* __restrict__ lam, float* __restrict__ out) {
    __shared__ float s_w[1600], s_in[16 * 432];
    const int tid = threadIdx.x, x = tid & 31, yy = tid >> 5;
    const int n = blockIdx.z, tx0 = blockIdx.x * 32, ty0 = blockIdx.y * 8;
    for (int i = tid; i < 1600; i += 256) s_w[i] = g_w0b[i];
    float acc = 0.f;
    for (int c0 = 0; c0 < 64; c0 += 16) {
        __syncthreads();
        for (int i = tid; i < 6912; i += 256) {
            int cc = i & 15, j = i >> 4;
            int py = j / 36, px = j - py * 36;
            int gy = ty0 + py - 2, gx = tx0 + px - 2;
            float vv = 0.f;
            if (gy >= 0 && gy < 128 && gx >= 0 && gx < 128) {
                size_t o = ((size_t)n * HW + (size_t)gy * 128 + gx) * 64 + c0 + cc;
                vv = __bfloat162float(inH[o]) + __bfloat162float(inL[o]);
            }
            s_in[cc * 432 + j] = vv;
        }
        __syncthreads();
#pragma unroll
        for (int cc = 0; cc < 16; cc++) {
            const float* wp = &s_w[(c0 + cc) * 25];
            const float* pin = s_in + cc * 432;
#pragma unroll
            for (int u = 0; u < 5; u++)
#pragma unroll
                for (int v = 0; v < 5; v++)
                    acc += pin[(yy + u) * 36 + x + v] * wp[u * 5 + v];
        }
    }
    size_t idx = (size_t)n * HW + (size_t)(ty0 + yy) * 128 + tx0 + x;
    float xv = xin[idx], yv = yin[idx];
    out[idx] = xv - acc * (1.f / 255.f) - __expf(lam[0]) * (xv - yv);
}

// ---- launch --------------------------------------------------------------
extern "C" void kernel_launch(void* const* d_in, const int* in_sizes, int n_in,
                              void* d_out, int out_size) {
    const float *x = nullptr, *y = nullptr, *lam = nullptr, *f0 = nullptr,
                *fr = nullptr, *bias = nullptr, *actw = nullptr;
    for (int i = 0; i < n_in; i++) {
        const float* p = (const float*)d_in[i];
        switch (in_sizes[i]) {
            case 65536: if (!x) x = p; else y = p; break;
            case 1: lam = p; break;
            case 1600: f0 = p; break;
            case 307200: fr = p; break;
            case 256: bias = p; break;
            case 16128: actw = p; break;
            default: break;
        }
    }
    void *pAh, *pAl, *pBh, *pBl, *pT, *pW, *pact;
    cudaGetSymbolAddress(&pAh, g_Ah); cudaGetSymbolAddress(&pAl, g_Al);
    cudaGetSymbolAddress(&pBh, g_Bh); cudaGetSymbolAddress(&pBl, g_Bl);
    cudaGetSymbolAddress(&pT, g_T);   cudaGetSymbolAddress(&pW, g_wbf);
    cudaGetSymbolAddress(&pact, g_actp);
    bf *Ah = (bf*)pAh, *Al = (bf*)pAl, *Bh = (bf*)pBh, *Bl = (bf*)pBl;
    float *T = (float*)pT, *act = (float*)pact;
    bf *W = (bf*)pW;

    cudaFuncSetAttribute(mma_conv<false, true >, cudaFuncAttributeMaxDynamicSharedMemorySize, DSMEM);
    cudaFuncSetAttribute(mma_conv<false, false>, cudaFuncAttributeMaxDynamicSharedMemorySize, DSMEM);
    cudaFuncSetAttribute(mma_conv<true,  false>, cudaFuncAttributeMaxDynamicSharedMemorySize, DSMEM);

    dim3 gs(4, 16, 4), gm(128, 1, 4), blk(256);
    prep_kernel<<<1200, 256>>>(f0, fr, actw);
    conv0_kernel<<<gs, blk>>>(x, bias, T, Ah, Al);
    // forward layers 1..3 (weights ld0..2)
    mma_conv<false, true ><<<gm, blk, DSMEM>>>(Ah, Al, W,            bias + 64,  act + 5120,     nullptr, T + (size_t)NCHW, Bh, Bl);
    mma_conv<false, true ><<<gm, blk, DSMEM>>>(Bh, Bl, W + LWBF,     bias + 128, act + 2 * 5120, nullptr, T + 2ull * NCHW,  Ah, Al);
    mma_conv<false, false><<<gm, blk, DSMEM>>>(Ah, Al, W + 2 * LWBF, bias + 192, act + 3 * 5120, nullptr, nullptr,          Bh, Bl);
    // backward: convT(w3) gate t2, convT(w2) gate t1, convT(w1) gate t0
    mma_conv<true, false><<<gm, blk, DSMEM>>>(Bh, Bl, W + 5 * LWBF, nullptr, act + 2 * 5120, T + 2ull * NCHW,  nullptr, Ah, Al);
    mma_conv<true, false><<<gm, blk, DSMEM>>>(Ah, Al, W + 4 * LWBF, nullptr, act + 5120,     T + (size_t)NCHW, nullptr, Bh, Bl);
    mma_conv<true, false><<<gm, blk, DSMEM>>>(Bh, Bl, W + 3 * LWBF, nullptr, act,            T,                nullptr, Ah, Al);
    final_kernel<<<gs, blk>>>(Ah, Al, x, y, lam, (float*)d_out);
}